// round 10
// baseline (speedup 1.0000x reference)
#include <cuda_runtime.h>
#include <cstdint>

#define NS 512
#define NV 32000
#define NB 16
#define NT 128
#define NBC 4   // batches (independent recurrences) per cluster

// ---- scratch (no cudaMalloc allowed) ----
__device__ float g_lse_em[NS];
__device__ float g_pi[NS];
__device__ float g_PT[NS * NS];          // PT[c][s] = softmax(tm)[s][c]
__device__ float g_E[NB * NT * NS];      // E[b][t][s] = exp(log_em[s, x_bt])
__device__ float g_L[NB];                // per-batch log-likelihood

// ---- helpers ----
__device__ __forceinline__ unsigned smem_u32(const void* p) {
    return (unsigned)__cvta_generic_to_shared(p);
}
__device__ __forceinline__ unsigned mapa_u32(unsigned local, unsigned rank) {
    unsigned r;
    asm("mapa.shared::cluster.u32 %0, %1, %2;" : "=r"(r) : "r"(local), "r"(rank));
    return r;
}
#define MBAR_INIT(mb, cnt) \
    asm volatile("mbarrier.init.shared.b64 [%0], %1;" :: "r"(mb), "r"(cnt) : "memory")
#define MBAR_EXPECT_TX(mb, bytes) \
    asm volatile("mbarrier.arrive.expect_tx.shared.b64 _, [%0], %1;" :: "r"(mb), "r"(bytes) : "memory")
// HW-sleep wait (suspend hint keeps spinners off the SMEM port)
#define MBAR_WAIT_CLUSTER(mb, parity) do {                                                       \
    asm volatile("{\n\t.reg .pred P;\n\tW%=:\n\t"                                                \
        "mbarrier.try_wait.parity.acquire.cluster.shared::cta.b64 P, [%0], %1, 0x989680;\n\t"    \
        "@!P bra W%=;\n\t}" :: "r"(mb), "r"(parity) : "memory");                                 \
} while (0)
__device__ __forceinline__ void st_async_v4(unsigned raddr, float4 v, unsigned rmbar) {
    asm volatile(
        "st.async.shared::cluster.mbarrier::complete_tx::bytes.v4.f32 "
        "[%0], {%1, %2, %3, %4}, [%5];"
        :: "r"(raddr), "f"(v.x), "f"(v.y), "f"(v.z), "f"(v.w), "r"(rmbar) : "memory");
}
// packed f32x2 math
#define FMA2(d, a, b, c) \
    asm("fma.rn.f32x2 %0, %1, %2, %3;" : "=l"(d) : "l"(a), "l"(b), "l"(c))
#define ADD2(d, a, b) \
    asm("add.rn.f32x2 %0, %1, %2;" : "=l"(d) : "l"(a), "l"(b))
__device__ __forceinline__ float hadd2(unsigned long long v) {
    float lo, hi;
    asm("mov.b64 {%0, %1}, %2;" : "=f"(lo), "=f"(hi) : "l"(v));
    return lo + hi;
}

// ===================== K1: row logsumexp of em [512, 32000] =====================
__global__ void k_lse_em(const float* __restrict__ em) {
    const int row = blockIdx.x;
    const float4* r = (const float4*)(em + (size_t)row * NV);
    const int n4 = NV / 4;  // 8000

    __shared__ float sm[8];

    float m = -1e30f;
    for (int i = threadIdx.x; i < n4; i += blockDim.x) {
        float4 x = r[i];
        m = fmaxf(m, fmaxf(fmaxf(x.x, x.y), fmaxf(x.z, x.w)));
    }
    #pragma unroll
    for (int o = 16; o; o >>= 1) m = fmaxf(m, __shfl_xor_sync(~0u, m, o));
    if ((threadIdx.x & 31) == 0) sm[threadIdx.x >> 5] = m;
    __syncthreads();
    if (threadIdx.x < 32) {
        float mm = (threadIdx.x < (blockDim.x >> 5)) ? sm[threadIdx.x] : -1e30f;
        #pragma unroll
        for (int o = 4; o; o >>= 1) mm = fmaxf(mm, __shfl_xor_sync(~0u, mm, o));
        if (threadIdx.x == 0) sm[0] = mm;
    }
    __syncthreads();
    m = sm[0];
    __syncthreads();

    float s = 0.f;
    for (int i = threadIdx.x; i < n4; i += blockDim.x) {
        float4 x = r[i];
        s += __expf(x.x - m) + __expf(x.y - m) + __expf(x.z - m) + __expf(x.w - m);
    }
    #pragma unroll
    for (int o = 16; o; o >>= 1) s += __shfl_xor_sync(~0u, s, o);
    if ((threadIdx.x & 31) == 0) sm[threadIdx.x >> 5] = s;
    __syncthreads();
    if (threadIdx.x == 0) {
        float tot = 0.f;
        for (int wi = 0; wi < (blockDim.x >> 5); wi++) tot += sm[wi];
        g_lse_em[row] = m + __logf(tot);
    }
}

// ===================== K2: P^T = softmax(tm) transposed; pi = softmax(p) ========
__global__ void k_tm_pi(const float* __restrict__ tm, const float* __restrict__ p) {
    __shared__ float sm[4];
    __shared__ float red;
    const int tid = threadIdx.x;  // 128 threads

    const float* src = (blockIdx.x < NS) ? (tm + (size_t)blockIdx.x * NS) : p;

    float m = -1e30f;
    #pragma unroll
    for (int k = 0; k < 4; k++) m = fmaxf(m, src[tid + 128 * k]);
    #pragma unroll
    for (int o = 16; o; o >>= 1) m = fmaxf(m, __shfl_xor_sync(~0u, m, o));
    if ((tid & 31) == 0) sm[tid >> 5] = m;
    __syncthreads();
    if (tid == 0) red = fmaxf(fmaxf(sm[0], sm[1]), fmaxf(sm[2], sm[3]));
    __syncthreads();
    m = red;

    float s = 0.f;
    #pragma unroll
    for (int k = 0; k < 4; k++) s += __expf(src[tid + 128 * k] - m);
    #pragma unroll
    for (int o = 16; o; o >>= 1) s += __shfl_xor_sync(~0u, s, o);
    if ((tid & 31) == 0) sm[tid >> 5] = s;
    __syncthreads();
    if (tid == 0) red = m + __logf(sm[0] + sm[1] + sm[2] + sm[3]);
    __syncthreads();
    const float lse = red;

    if (blockIdx.x < NS) {
        const int row = blockIdx.x;  // source state s
        #pragma unroll
        for (int k = 0; k < 4; k++) {
            int c = tid + 128 * k;   // dest state
            g_PT[(size_t)c * NS + row] = __expf(src[c] - lse);
        }
    } else {
        #pragma unroll
        for (int k = 0; k < 4; k++) {
            int i = tid + 128 * k;
            g_pi[i] = __expf(p[i] - lse);
        }
    }
}

// ===================== K3: gather E[b][t][s] = exp(em[s, id] - lse_em[s]) =======
__global__ void k_gather(const float* __restrict__ em, const int* __restrict__ ids) {
    const int bt = blockIdx.x;           // 0..2047
    int id = ids[bt];
    id = (id < 0) ? 0 : ((id >= NV) ? NV - 1 : id);
    const float* col = em + id;
    #pragma unroll
    for (int k = 0; k < 4; k++) {
        int s = threadIdx.x + 128 * k;   // blockDim = 128
        g_E[(size_t)bt * NS + s] = __expf(col[(size_t)s * NV] - g_lse_em[s]);
    }
}

// ===================== K4: clustered multi-batch scaled-forward recurrence ======
// 4 clusters x 8 CTAs x 512 threads; each cluster runs NBC=4 INDEPENDENT batch
// recurrences interleaved, sharing the same register-resident P^T chunk.
// While batch A's DSMEM push is in flight, the warp computes batches B/C/D:
// the exchange latency (invariant ~2.2us/step across R4-R8 mechanisms) is
// hidden behind the other batches' compute.
// R9 bugfix: phase flip must happen ONLY when a wait actually occurred (t>=2);
// the unconditional flip at t=1 desynced parity -> deadlock.
__global__ void __cluster_dims__(8, 1, 1) __launch_bounds__(512, 1) k_forward() {
    __shared__ __align__(16) float buf[NBC][2][NS];
    __shared__ __align__(8) unsigned long long mbars[NBC][2];

    const int tid = threadIdx.x;
    const int l = tid & 31;
    unsigned rank;
    asm("mov.u32 %0, %%cluster_ctarank;" : "=r"(rank));
    const int g0 = (blockIdx.x >> 3) * NBC;               // first batch of cluster
    const int colbase = (int)rank * 64 + (tid >> 5) * 4;  // this warp's 4 columns

    // --- P^T chunk into packed registers (shared by all NBC batches) ---
    unsigned long long Pa[4][4], Pb[4][4];
    #pragma unroll
    for (int j = 0; j < 4; j++)
        #pragma unroll
        for (int k = 0; k < 4; k++) {
            ulonglong2 pp = *(const ulonglong2*)&g_PT[(size_t)(colbase + j) * NS + 4 * l + 128 * k];
            Pa[j][k] = pp.x;
            Pb[j][k] = pp.y;
        }

    const unsigned mb_base = smem_u32(&mbars[0][0]);
    if (tid == 0) {
        #pragma unroll
        for (int i = 0; i < NBC * 2; i++) MBAR_INIT(mb_base + i * 8, 1);
    }

    const float* Eb = g_E + (size_t)g0 * NT * NS;

    // --- t = 0: every CTA computes full v0 = pi * E0 locally, per batch ---
    {
        const float pi = g_pi[tid];
        #pragma unroll
        for (int b = 0; b < NBC; b++)
            buf[b][0][tid] = pi * Eb[b * NT * NS + tid];
    }
    __syncthreads();
    // peers' mbarriers must be initialized before any st.async targets them
    asm volatile("barrier.cluster.arrive.aligned;" ::: "memory");
    asm volatile("barrier.cluster.wait.aligned;"   ::: "memory");

    // --- per-lane remote base addresses (lanes 0..7 push to peer = lane index) ---
    unsigned rbuf = 0, rmb = 0;
    if (l < 8) {
        rbuf = mapa_u32(smem_u32(&buf[0][0][0]), (unsigned)l);
        rmb  = mapa_u32(mb_base, (unsigned)l);
    }

    int ph0 = 0, ph1 = 0;
    float L[NBC];
    #pragma unroll
    for (int b = 0; b < NBC; b++) L[b] = 0.f;

    for (int t = 1; t < NT; t++) {
        const int sp = (t - 1) & 1;         // slot holding v_{t-1}
        const int sc = t & 1;               // slot receiving v_t
        const int parity = sp ? ph1 : ph0;

        #pragma unroll
        for (int b = 0; b < NBC; b++) {
            const unsigned mbp = mb_base + (unsigned)((b * 2 + sp) * 8);
            const unsigned mbc = mb_base + (unsigned)((b * 2 + sc) * 8);
            // wait for this batch's v_{t-1} (t==1: local from init)
            if (t >= 2) MBAR_WAIT_CLUSTER(mbp, parity);
            // arm this batch's receive barrier: 8 ranks x 16 warps x 16 B
            if (tid == 0) MBAR_EXPECT_TX(mbc, 2048u);

            // emission factors (issued early; consumed after the dot)
            const float4 e4 = *(const float4*)&Eb[b * NT * NS + t * NS + colbase];

            // packed dot over the 512-vector + packed S_prev sum
            const float* cur = buf[b][sp];
            unsigned long long acc0 = 0, acc1 = 0, acc2 = 0, acc3 = 0, ssp = 0;
            #pragma unroll
            for (int k = 0; k < 4; k++) {
                ulonglong2 aa = *(const ulonglong2*)&cur[4 * l + 128 * k];
                FMA2(acc0, aa.x, Pa[0][k], acc0); FMA2(acc0, aa.y, Pb[0][k], acc0);
                FMA2(acc1, aa.x, Pa[1][k], acc1); FMA2(acc1, aa.y, Pb[1][k], acc1);
                FMA2(acc2, aa.x, Pa[2][k], acc2); FMA2(acc2, aa.y, Pb[2][k], acc2);
                FMA2(acc3, aa.x, Pa[3][k], acc3); FMA2(acc3, aa.y, Pb[3][k], acc3);
                ADD2(ssp, ssp, aa.x); ADD2(ssp, ssp, aa.y);
            }
            float a0 = hadd2(acc0), a1 = hadd2(acc1), a2 = hadd2(acc2), a3 = hadd2(acc3);
            float ss = hadd2(ssp);
            #pragma unroll
            for (int o = 16; o; o >>= 1) {
                a0 += __shfl_xor_sync(~0u, a0, o);
                a1 += __shfl_xor_sync(~0u, a1, o);
                a2 += __shfl_xor_sync(~0u, a2, o);
                a3 += __shfl_xor_sync(~0u, a3, o);
                ss += __shfl_xor_sync(~0u, ss, o);
            }
            // ss == S_{t-1}; identical across all warps & CTAs of the cluster
            const float invS = __fdividef(1.f, ss);

            // push this warp's 4 scaled columns to all 8 CTAs (lane r -> peer r)
            if (l < 8) {
                float4 v;
                v.x = a0 * invS * e4.x;
                v.y = a1 * invS * e4.y;
                v.z = a2 * invS * e4.z;
                v.w = a3 * invS * e4.w;
                const unsigned daddr =
                    rbuf + (unsigned)(((b * 2 + sc) * NS + colbase) * 4);
                st_async_v4(daddr, v, rmb + (unsigned)((b * 2 + sc) * 8));
            }
            if (rank == 0 && tid == 0) L[b] += __logf(ss);
        }
        // flip ONLY if a wait actually consumed a phase this iteration (t>=2)
        if (t >= 2) { if (sp) ph1 ^= 1; else ph0 ^= 1; }
    }

    // --- final S_{T-1} terms: v_127 lives in slot 1 / mbar[b][1] ---
    // mb[b][1] armings: t=1,3,...,127 -> 64th phase = parity 63&1 = 1.
    // ph1 flips at waits t=2,4,...,126 (63 flips) -> ph1 == 1 here. Consistent.
    #pragma unroll
    for (int b = 0; b < NBC; b++) {
        MBAR_WAIT_CLUSTER(mb_base + (unsigned)((b * 2 + 1) * 8), ph1);
        const float* cur = buf[b][1];
        unsigned long long ssp = 0;
        #pragma unroll
        for (int k = 0; k < 4; k++) {
            ulonglong2 aa = *(const ulonglong2*)&cur[4 * l + 128 * k];
            ADD2(ssp, ssp, aa.x); ADD2(ssp, ssp, aa.y);
        }
        float ss = hadd2(ssp);
        #pragma unroll
        for (int o = 16; o; o >>= 1) ss += __shfl_xor_sync(~0u, ss, o);
        if (rank == 0 && tid == 0) g_L[g0 + b] = L[b] + __logf(ss);
    }
    // align exits: no CTA leaves while a peer could still target its smem
    asm volatile("barrier.cluster.arrive.aligned;" ::: "memory");
    asm volatile("barrier.cluster.wait.aligned;"   ::: "memory");
}

// ===================== K5: loss = -mean_b L[b] ===================================
__global__ void k_final(float* __restrict__ out) {
    if (threadIdx.x == 0) {
        float s = 0.f;
        #pragma unroll
        for (int i = 0; i < NB; i++) s += g_L[i];
        out[0] = -s / (float)NB;
    }
}

// ===================== launch ====================================================
extern "C" void kernel_launch(void* const* d_in, const int* in_sizes, int n_in,
                              void* d_out, int out_size) {
    const float* em = nullptr;
    const float* tm = nullptr;
    const float* p  = nullptr;
    const int* ids  = nullptr;
    for (int i = 0; i < n_in; i++) {
        if (in_sizes[i] == NB * NT)      ids = (const int*)d_in[i];
        else if (in_sizes[i] == NS * NV) em  = (const float*)d_in[i];
        else if (in_sizes[i] == NS * NS) tm  = (const float*)d_in[i];
        else if (in_sizes[i] == NS)      p   = (const float*)d_in[i];
    }

    k_lse_em<<<NS, 256>>>(em);
    k_tm_pi<<<NS + 1, 128>>>(tm, p);
    k_gather<<<NB * NT, 128>>>(em, ids);

    {
        cudaLaunchConfig_t cfg = {};
        cfg.gridDim  = dim3((NB / NBC) * 8, 1, 1);
        cfg.blockDim = dim3(512, 1, 1);
        cfg.dynamicSmemBytes = 0;
        cfg.stream = 0;
        cudaLaunchAttribute attrs[1];
        attrs[0].id = cudaLaunchAttributeClusterDimension;
        attrs[0].val.clusterDim.x = 8;
        attrs[0].val.clusterDim.y = 1;
        attrs[0].val.clusterDim.z = 1;
        cfg.attrs = attrs;
        cfg.numAttrs = 1;
        cudaLaunchKernelEx(&cfg, k_forward);
    }

    k_final<<<1, 32>>>((float*)d_out);
}

// round 11
// speedup vs baseline: 1.2564x; 1.2564x over previous
#include <cuda_runtime.h>
#include <cstdint>

#define NS 512
#define NV 32000
#define NB 16
#define NT 128

// ---- scratch (no cudaMalloc allowed) ----
__device__ float g_lse_em[NS];
__device__ float g_pi[NS];
__device__ float g_PT[NS * NS];          // PT[c][s] = softmax(tm)[s][c]
__device__ float g_E[NB * NT * NS];      // E[b][t][s] = exp(log_em[s, x_bt])
__device__ float g_L[NB];                // per-batch log-likelihood

// ---- helpers ----
__device__ __forceinline__ unsigned smem_u32(const void* p) {
    return (unsigned)__cvta_generic_to_shared(p);
}
__device__ __forceinline__ unsigned mapa_u32(unsigned local, unsigned rank) {
    unsigned r;
    asm("mapa.shared::cluster.u32 %0, %1, %2;" : "=r"(r) : "r"(local), "r"(rank));
    return r;
}
// plain remote SMEM store (ordered by barrier.cluster release/acquire)
__device__ __forceinline__ void st_cluster_v4(unsigned raddr, float4 v) {
    asm volatile("st.shared::cluster.v4.f32 [%0], {%1, %2, %3, %4};"
                 :: "r"(raddr), "f"(v.x), "f"(v.y), "f"(v.z), "f"(v.w) : "memory");
}
#define CLUSTER_ARRIVE() asm volatile("barrier.cluster.arrive.aligned;" ::: "memory")
#define CLUSTER_WAIT()   asm volatile("barrier.cluster.wait.aligned;"   ::: "memory")
// packed f32x2 math
#define FMA2(d, a, b, c) \
    asm("fma.rn.f32x2 %0, %1, %2, %3;" : "=l"(d) : "l"(a), "l"(b), "l"(c))
#define ADD2(d, a, b) \
    asm("add.rn.f32x2 %0, %1, %2;" : "=l"(d) : "l"(a), "l"(b))
__device__ __forceinline__ float hadd2(unsigned long long v) {
    float lo, hi;
    asm("mov.b64 {%0, %1}, %2;" : "=f"(lo), "=f"(hi) : "l"(v));
    return lo + hi;
}

// ===================== K1: row logsumexp of em [512, 32000] =====================
__global__ void k_lse_em(const float* __restrict__ em) {
    const int row = blockIdx.x;
    const float4* r = (const float4*)(em + (size_t)row * NV);
    const int n4 = NV / 4;  // 8000

    __shared__ float sm[8];

    float m = -1e30f;
    for (int i = threadIdx.x; i < n4; i += blockDim.x) {
        float4 x = r[i];
        m = fmaxf(m, fmaxf(fmaxf(x.x, x.y), fmaxf(x.z, x.w)));
    }
    #pragma unroll
    for (int o = 16; o; o >>= 1) m = fmaxf(m, __shfl_xor_sync(~0u, m, o));
    if ((threadIdx.x & 31) == 0) sm[threadIdx.x >> 5] = m;
    __syncthreads();
    if (threadIdx.x < 32) {
        float mm = (threadIdx.x < (blockDim.x >> 5)) ? sm[threadIdx.x] : -1e30f;
        #pragma unroll
        for (int o = 4; o; o >>= 1) mm = fmaxf(mm, __shfl_xor_sync(~0u, mm, o));
        if (threadIdx.x == 0) sm[0] = mm;
    }
    __syncthreads();
    m = sm[0];
    __syncthreads();

    float s = 0.f;
    for (int i = threadIdx.x; i < n4; i += blockDim.x) {
        float4 x = r[i];
        s += __expf(x.x - m) + __expf(x.y - m) + __expf(x.z - m) + __expf(x.w - m);
    }
    #pragma unroll
    for (int o = 16; o; o >>= 1) s += __shfl_xor_sync(~0u, s, o);
    if ((threadIdx.x & 31) == 0) sm[threadIdx.x >> 5] = s;
    __syncthreads();
    if (threadIdx.x == 0) {
        float tot = 0.f;
        for (int wi = 0; wi < (blockDim.x >> 5); wi++) tot += sm[wi];
        g_lse_em[row] = m + __logf(tot);
    }
}

// ===================== K2: P^T = softmax(tm) transposed; pi = softmax(p) ========
__global__ void k_tm_pi(const float* __restrict__ tm, const float* __restrict__ p) {
    __shared__ float sm[4];
    __shared__ float red;
    const int tid = threadIdx.x;  // 128 threads

    const float* src = (blockIdx.x < NS) ? (tm + (size_t)blockIdx.x * NS) : p;

    float m = -1e30f;
    #pragma unroll
    for (int k = 0; k < 4; k++) m = fmaxf(m, src[tid + 128 * k]);
    #pragma unroll
    for (int o = 16; o; o >>= 1) m = fmaxf(m, __shfl_xor_sync(~0u, m, o));
    if ((tid & 31) == 0) sm[tid >> 5] = m;
    __syncthreads();
    if (tid == 0) red = fmaxf(fmaxf(sm[0], sm[1]), fmaxf(sm[2], sm[3]));
    __syncthreads();
    m = red;

    float s = 0.f;
    #pragma unroll
    for (int k = 0; k < 4; k++) s += __expf(src[tid + 128 * k] - m);
    #pragma unroll
    for (int o = 16; o; o >>= 1) s += __shfl_xor_sync(~0u, s, o);
    if ((tid & 31) == 0) sm[tid >> 5] = s;
    __syncthreads();
    if (tid == 0) red = m + __logf(sm[0] + sm[1] + sm[2] + sm[3]);
    __syncthreads();
    const float lse = red;

    if (blockIdx.x < NS) {
        const int row = blockIdx.x;  // source state s
        #pragma unroll
        for (int k = 0; k < 4; k++) {
            int c = tid + 128 * k;   // dest state
            g_PT[(size_t)c * NS + row] = __expf(src[c] - lse);
        }
    } else {
        #pragma unroll
        for (int k = 0; k < 4; k++) {
            int i = tid + 128 * k;
            g_pi[i] = __expf(p[i] - lse);
        }
    }
}

// ===================== K3: gather E[b][t][s] = exp(em[s, id] - lse_em[s]) =======
__global__ void k_gather(const float* __restrict__ em, const int* __restrict__ ids) {
    const int bt = blockIdx.x;           // 0..2047
    int id = ids[bt];
    id = (id < 0) ? 0 : ((id >= NV) ? NV - 1 : id);
    const float* col = em + id;
    #pragma unroll
    for (int k = 0; k < 4; k++) {
        int s = threadIdx.x + 128 * k;   // blockDim = 128
        g_E[(size_t)bt * NS + s] = __expf(col[(size_t)s * NV] - g_lse_em[s]);
    }
}

// ===================== K4: clustered scaled-forward recurrence ==================
// 16 clusters (one per batch) x 8 CTAs x 512 threads. Each CTA owns 64 output
// columns; its 64x512 P^T chunk lives in packed f32x2 registers.
// Per step: local LDS dot + packed S-sum -> butterfly -> scale -> lanes 0..7
// push the warp's 4 scaled columns to all 8 peers with PLAIN st.shared::cluster
// -> barrier.cluster.arrive (release drains the stores) -> __logf hidden in the
// barrier window -> barrier.cluster.wait (acquire). No mbarriers, no tx-count
// machinery (the suspected ~1.4us/step overhead of R4-R8 exchange schemes).
__global__ void __cluster_dims__(8, 1, 1) __launch_bounds__(512, 1) k_forward() {
    __shared__ __align__(16) float buf[2][NS];

    const int tid = threadIdx.x;
    const int l = tid & 31;
    unsigned rank;
    asm("mov.u32 %0, %%cluster_ctarank;" : "=r"(rank));
    const int g = blockIdx.x >> 3;                        // batch / cluster id
    const int colbase = (int)rank * 64 + (tid >> 5) * 4;  // this warp's 4 columns

    // --- P^T chunk into packed registers:
    // Pa[j][k] = pair PT[colbase+j][4l+128k+{0,1}], Pb = +{2,3} ---
    unsigned long long Pa[4][4], Pb[4][4];
    #pragma unroll
    for (int j = 0; j < 4; j++)
        #pragma unroll
        for (int k = 0; k < 4; k++) {
            ulonglong2 pp = *(const ulonglong2*)&g_PT[(size_t)(colbase + j) * NS + 4 * l + 128 * k];
            Pa[j][k] = pp.x;
            Pb[j][k] = pp.y;
        }

    const float* Eb = g_E + (size_t)g * NT * NS;

    // --- t = 0: every CTA computes the full v0 = pi * E0 locally ---
    buf[0][tid] = g_pi[tid] * Eb[tid];
    __syncthreads();
    CLUSTER_ARRIVE();
    CLUSTER_WAIT();

    // --- per-lane remote buf base (lanes 0..7 push to peer = lane index) ---
    unsigned rbuf = 0;
    if (l < 8) rbuf = mapa_u32(smem_u32(&buf[0][0]), (unsigned)l);

    float L = 0.f;

    for (int t = 1; t < NT; t++) {
        const int sp = (t - 1) & 1;   // slot holding v_{t-1}
        const int sc = t & 1;         // slot receiving v_t

        // emission factors for this warp's 4 columns (independent LDG, issued
        // early, consumed ~500 cyc later after the dot+butterfly)
        const float4 e4 = *(const float4*)&Eb[t * NS + colbase];

        // packed dot over the 512-vector + packed S_prev sum
        const float* cur = buf[sp];
        unsigned long long acc0 = 0, acc1 = 0, acc2 = 0, acc3 = 0, ssp = 0;
        #pragma unroll
        for (int k = 0; k < 4; k++) {
            ulonglong2 aa = *(const ulonglong2*)&cur[4 * l + 128 * k];
            FMA2(acc0, aa.x, Pa[0][k], acc0); FMA2(acc0, aa.y, Pb[0][k], acc0);
            FMA2(acc1, aa.x, Pa[1][k], acc1); FMA2(acc1, aa.y, Pb[1][k], acc1);
            FMA2(acc2, aa.x, Pa[2][k], acc2); FMA2(acc2, aa.y, Pb[2][k], acc2);
            FMA2(acc3, aa.x, Pa[3][k], acc3); FMA2(acc3, aa.y, Pb[3][k], acc3);
            ADD2(ssp, ssp, aa.x); ADD2(ssp, ssp, aa.y);
        }
        float a0 = hadd2(acc0), a1 = hadd2(acc1), a2 = hadd2(acc2), a3 = hadd2(acc3);
        float ss = hadd2(ssp);
        #pragma unroll
        for (int o = 16; o; o >>= 1) {
            a0 += __shfl_xor_sync(~0u, a0, o);
            a1 += __shfl_xor_sync(~0u, a1, o);
            a2 += __shfl_xor_sync(~0u, a2, o);
            a3 += __shfl_xor_sync(~0u, a3, o);
            ss += __shfl_xor_sync(~0u, ss, o);
        }
        // ss == S_{t-1}; identical across all warps & CTAs of the cluster
        const float invS = __fdividef(1.f, ss);

        // push this warp's 4 scaled columns to all 8 CTAs (lane r -> peer r)
        if (l < 8) {
            float4 v;
            v.x = a0 * invS * e4.x;
            v.y = a1 * invS * e4.y;
            v.z = a2 * invS * e4.z;
            v.w = a3 * invS * e4.w;
            st_cluster_v4(rbuf + (unsigned)((sc * NS + colbase) * 4), v);
        }
        // release our stores, then hide the logf inside the barrier window
        CLUSTER_ARRIVE();
        L += __logf(ss);     // ALL threads: uniform work, no rank/warp skew
        CLUSTER_WAIT();
    }

    // --- final S_{T-1} term: v_127 lives in slot 1 (visible after last wait) ---
    {
        const float* cur = buf[1];
        unsigned long long ssp = 0;
        #pragma unroll
        for (int k = 0; k < 4; k++) {
            ulonglong2 aa = *(const ulonglong2*)&cur[4 * l + 128 * k];
            ADD2(ssp, ssp, aa.x); ADD2(ssp, ssp, aa.y);
        }
        float ss = hadd2(ssp);
        #pragma unroll
        for (int o = 16; o; o >>= 1) ss += __shfl_xor_sync(~0u, ss, o);
        if (rank == 0 && tid == 0) g_L[g] = L + __logf(ss);
    }
    // no remote ops after the loop's final barrier -> safe to exit
}

// ===================== K5: loss = -mean_b L[b] ===================================
__global__ void k_final(float* __restrict__ out) {
    if (threadIdx.x == 0) {
        float s = 0.f;
        #pragma unroll
        for (int i = 0; i < NB; i++) s += g_L[i];
        out[0] = -s / (float)NB;
    }
}

// ===================== launch ====================================================
extern "C" void kernel_launch(void* const* d_in, const int* in_sizes, int n_in,
                              void* d_out, int out_size) {
    const float* em = nullptr;
    const float* tm = nullptr;
    const float* p  = nullptr;
    const int* ids  = nullptr;
    for (int i = 0; i < n_in; i++) {
        if (in_sizes[i] == NB * NT)      ids = (const int*)d_in[i];
        else if (in_sizes[i] == NS * NV) em  = (const float*)d_in[i];
        else if (in_sizes[i] == NS * NS) tm  = (const float*)d_in[i];
        else if (in_sizes[i] == NS)      p   = (const float*)d_in[i];
    }

    k_lse_em<<<NS, 256>>>(em);
    k_tm_pi<<<NS + 1, 128>>>(tm, p);
    k_gather<<<NB * NT, 128>>>(em, ids);

    {
        cudaLaunchConfig_t cfg = {};
        cfg.gridDim  = dim3(NB * 8, 1, 1);
        cfg.blockDim = dim3(512, 1, 1);
        cfg.dynamicSmemBytes = 0;
        cfg.stream = 0;
        cudaLaunchAttribute attrs[1];
        attrs[0].id = cudaLaunchAttributeClusterDimension;
        attrs[0].val.clusterDim.x = 8;
        attrs[0].val.clusterDim.y = 1;
        attrs[0].val.clusterDim.z = 1;
        cfg.attrs = attrs;
        cfg.numAttrs = 1;
        cudaLaunchKernelEx(&cfg, k_forward);
    }

    k_final<<<1, 32>>>((float*)d_out);
}

// round 12
// speedup vs baseline: 1.4631x; 1.1646x over previous
#include <cuda_runtime.h>
#include <cstdint>

#define NS 512
#define NV 32000
#define NB 16
#define NT 128

// ---- scratch (no cudaMalloc allowed) ----
__device__ float g_lse_em[NS];
__device__ float g_pi[NS];
__device__ float g_PT[NS * NS];          // PT[c][s] = softmax(tm)[s][c]
__device__ float g_E[NB * NT * NS];      // E[b][t][s] = exp(log_em[s, x_bt])
__device__ float g_L[NB];                // per-batch log-likelihood

// ---- helpers ----
__device__ __forceinline__ unsigned smem_u32(const void* p) {
    return (unsigned)__cvta_generic_to_shared(p);
}
__device__ __forceinline__ unsigned mapa_u32(unsigned local, unsigned rank) {
    unsigned r;
    asm("mapa.shared::cluster.u32 %0, %1, %2;" : "=r"(r) : "r"(local), "r"(rank));
    return r;
}
#define MBAR_INIT(mb, cnt) \
    asm volatile("mbarrier.init.shared.b64 [%0], %1;" :: "r"(mb), "r"(cnt) : "memory")
#define MBAR_EXPECT_TX(mb, bytes) \
    asm volatile("mbarrier.arrive.expect_tx.shared.b64 _, [%0], %1;" :: "r"(mb), "r"(bytes) : "memory")
// HW-sleep wait (suspend hint keeps spinners off the SMEM port)
#define MBAR_WAIT_CLUSTER(mb, parity) do {                                                       \
    asm volatile("{\n\t.reg .pred P;\n\tW%=:\n\t"                                                \
        "mbarrier.try_wait.parity.acquire.cluster.shared::cta.b64 P, [%0], %1, 0x989680;\n\t"    \
        "@!P bra W%=;\n\t}" :: "r"(mb), "r"(parity) : "memory");                                 \
} while (0)
__device__ __forceinline__ void st_async_v4(unsigned raddr, float4 v, unsigned rmbar) {
    asm volatile(
        "st.async.shared::cluster.mbarrier::complete_tx::bytes.v4.f32 "
        "[%0], {%1, %2, %3, %4}, [%5];"
        :: "r"(raddr), "f"(v.x), "f"(v.y), "f"(v.z), "f"(v.w), "r"(rmbar) : "memory");
}
// packed f32x2 math
#define FMA2(d, a, b, c) \
    asm("fma.rn.f32x2 %0, %1, %2, %3;" : "=l"(d) : "l"(a), "l"(b), "l"(c))
#define ADD2(d, a, b) \
    asm("add.rn.f32x2 %0, %1, %2;" : "=l"(d) : "l"(a), "l"(b))
__device__ __forceinline__ float hadd2(unsigned long long v) {
    float lo, hi;
    asm("mov.b64 {%0, %1}, %2;" : "=f"(lo), "=f"(hi) : "l"(v));
    return lo + hi;
}

// ===================== K1: row logsumexp of em [512, 32000] =====================
__global__ void k_lse_em(const float* __restrict__ em) {
    const int row = blockIdx.x;
    const float4* r = (const float4*)(em + (size_t)row * NV);
    const int n4 = NV / 4;  // 8000

    __shared__ float sm[8];

    float m = -1e30f;
    for (int i = threadIdx.x; i < n4; i += blockDim.x) {
        float4 x = r[i];
        m = fmaxf(m, fmaxf(fmaxf(x.x, x.y), fmaxf(x.z, x.w)));
    }
    #pragma unroll
    for (int o = 16; o; o >>= 1) m = fmaxf(m, __shfl_xor_sync(~0u, m, o));
    if ((threadIdx.x & 31) == 0) sm[threadIdx.x >> 5] = m;
    __syncthreads();
    if (threadIdx.x < 32) {
        float mm = (threadIdx.x < (blockDim.x >> 5)) ? sm[threadIdx.x] : -1e30f;
        #pragma unroll
        for (int o = 4; o; o >>= 1) mm = fmaxf(mm, __shfl_xor_sync(~0u, mm, o));
        if (threadIdx.x == 0) sm[0] = mm;
    }
    __syncthreads();
    m = sm[0];
    __syncthreads();

    float s = 0.f;
    for (int i = threadIdx.x; i < n4; i += blockDim.x) {
        float4 x = r[i];
        s += __expf(x.x - m) + __expf(x.y - m) + __expf(x.z - m) + __expf(x.w - m);
    }
    #pragma unroll
    for (int o = 16; o; o >>= 1) s += __shfl_xor_sync(~0u, s, o);
    if ((threadIdx.x & 31) == 0) sm[threadIdx.x >> 5] = s;
    __syncthreads();
    if (threadIdx.x == 0) {
        float tot = 0.f;
        for (int wi = 0; wi < (blockDim.x >> 5); wi++) tot += sm[wi];
        g_lse_em[row] = m + __logf(tot);
    }
}

// ===================== K2: P^T = softmax(tm) transposed; pi = softmax(p) ========
__global__ void k_tm_pi(const float* __restrict__ tm, const float* __restrict__ p) {
    __shared__ float sm[4];
    __shared__ float red;
    const int tid = threadIdx.x;  // 128 threads

    const float* src = (blockIdx.x < NS) ? (tm + (size_t)blockIdx.x * NS) : p;

    float m = -1e30f;
    #pragma unroll
    for (int k = 0; k < 4; k++) m = fmaxf(m, src[tid + 128 * k]);
    #pragma unroll
    for (int o = 16; o; o >>= 1) m = fmaxf(m, __shfl_xor_sync(~0u, m, o));
    if ((tid & 31) == 0) sm[tid >> 5] = m;
    __syncthreads();
    if (tid == 0) red = fmaxf(fmaxf(sm[0], sm[1]), fmaxf(sm[2], sm[3]));
    __syncthreads();
    m = red;

    float s = 0.f;
    #pragma unroll
    for (int k = 0; k < 4; k++) s += __expf(src[tid + 128 * k] - m);
    #pragma unroll
    for (int o = 16; o; o >>= 1) s += __shfl_xor_sync(~0u, s, o);
    if ((tid & 31) == 0) sm[tid >> 5] = s;
    __syncthreads();
    if (tid == 0) red = m + __logf(sm[0] + sm[1] + sm[2] + sm[3]);
    __syncthreads();
    const float lse = red;

    if (blockIdx.x < NS) {
        const int row = blockIdx.x;  // source state s
        #pragma unroll
        for (int k = 0; k < 4; k++) {
            int c = tid + 128 * k;   // dest state
            g_PT[(size_t)c * NS + row] = __expf(src[c] - lse);
        }
    } else {
        #pragma unroll
        for (int k = 0; k < 4; k++) {
            int i = tid + 128 * k;
            g_pi[i] = __expf(p[i] - lse);
        }
    }
}

// ===================== K3: gather E[b][t][s] = exp(em[s, id] - lse_em[s]) =======
__global__ void k_gather(const float* __restrict__ em, const int* __restrict__ ids) {
    const int bt = blockIdx.x;           // 0..2047
    int id = ids[bt];
    id = (id < 0) ? 0 : ((id >= NV) ? NV - 1 : id);
    const float* col = em + id;
    #pragma unroll
    for (int k = 0; k < 4; k++) {
        int s = threadIdx.x + 128 * k;   // blockDim = 128
        g_E[(size_t)bt * NS + s] = __expf(col[(size_t)s * NV] - g_lse_em[s]);
    }
}

// ===================== K4: clustered scaled-forward recurrence ==================
// 16 clusters (one per batch) x 8 CTAs x 512 threads; P^T chunk in packed regs.
// Per step: ELECTED-WARP mbarrier wait + bar.sync broadcast (kills the 16x
// try_wait serialization on one mbar object) -> packed dot + packed S-sum ->
// reduce-scatter butterfly (6 shfls) + shfl.idx regather (4) + ss butterfly (5)
// -> scale -> lanes 0..7 st.async the warp's 4-col float4 to all 8 peers.
__global__ void __cluster_dims__(8, 1, 1) __launch_bounds__(512, 1) k_forward() {
    __shared__ __align__(16) float buf[2][NS];
    __shared__ __align__(8) unsigned long long mbars[2];

    const int tid = threadIdx.x;
    const int w = tid >> 5;
    const int l = tid & 31;
    unsigned rank;
    asm("mov.u32 %0, %%cluster_ctarank;" : "=r"(rank));
    const int g = blockIdx.x >> 3;                 // batch / cluster id
    const int colbase = (int)rank * 64 + w * 4;    // this warp's 4 columns

    // --- P^T chunk into packed registers ---
    unsigned long long Pa[4][4], Pb[4][4];
    #pragma unroll
    for (int j = 0; j < 4; j++)
        #pragma unroll
        for (int k = 0; k < 4; k++) {
            ulonglong2 pp = *(const ulonglong2*)&g_PT[(size_t)(colbase + j) * NS + 4 * l + 128 * k];
            Pa[j][k] = pp.x;
            Pb[j][k] = pp.y;
        }

    const unsigned mb0 = smem_u32(&mbars[0]);
    const unsigned mb1 = smem_u32(&mbars[1]);
    if (tid == 0) { MBAR_INIT(mb0, 1); MBAR_INIT(mb1, 1); }

    const float* Eb = g_E + (size_t)g * NT * NS;

    // --- t = 0: every CTA computes the full v0 = pi * E0 locally ---
    buf[0][tid] = g_pi[tid] * Eb[tid];
    __syncthreads();
    // peers' mbarriers must be initialized before any st.async targets them
    asm volatile("barrier.cluster.arrive.aligned;" ::: "memory");
    asm volatile("barrier.cluster.wait.aligned;"   ::: "memory");

    // --- per-lane remote addresses (lanes 0..7 push to peer = lane index) ---
    unsigned rbuf = 0, rmb0 = 0, rmb1 = 0;
    if (l < 8) {
        rbuf = mapa_u32(smem_u32(&buf[0][0]), (unsigned)l);
        rmb0 = mapa_u32(mb0, (unsigned)l);
        rmb1 = mapa_u32(mb1, (unsigned)l);
    }

    int ph0 = 0, ph1 = 0;
    float L = 0.f;
    float4 e4 = *(const float4*)&Eb[1 * NS + colbase];   // emission for t=1

    for (int t = 1; t < NT; t++) {
        const int sp = (t - 1) & 1;   // slot holding v_{t-1}
        const int sc = t & 1;         // slot receiving v_t

        // wait for v_{t-1}: ONLY warp 0 polls the mbarrier; bar.sync releases
        // (and memory-orders, cumulatively) the other 15 warps.
        if (t >= 2) {
            if (w == 0) {
                if (sp) MBAR_WAIT_CLUSTER(mb1, ph1);
                else    MBAR_WAIT_CLUSTER(mb0, ph0);
            }
            __syncthreads();
        }
        // arm this step's receive barrier (2048 B = 8 ranks x 16 warps x 16 B)
        if (tid == 0) MBAR_EXPECT_TX(sc ? mb1 : mb0, 2048u);

        // prefetch NEXT step's emission factors (off critical path)
        const int tn = (t + 1 < NT) ? t + 1 : t;
        const float4 e4n = *(const float4*)&Eb[tn * NS + colbase];

        // packed dot over the 512-vector + packed S_prev sum
        const float* cur = buf[sp];
        unsigned long long acc0 = 0, acc1 = 0, acc2 = 0, acc3 = 0, ssp = 0;
        #pragma unroll
        for (int k = 0; k < 4; k++) {
            ulonglong2 aa = *(const ulonglong2*)&cur[4 * l + 128 * k];
            FMA2(acc0, aa.x, Pa[0][k], acc0); FMA2(acc0, aa.y, Pb[0][k], acc0);
            FMA2(acc1, aa.x, Pa[1][k], acc1); FMA2(acc1, aa.y, Pb[1][k], acc1);
            FMA2(acc2, aa.x, Pa[2][k], acc2); FMA2(acc2, aa.y, Pb[2][k], acc2);
            FMA2(acc3, aa.x, Pa[3][k], acc3); FMA2(acc3, aa.y, Pb[3][k], acc3);
            ADD2(ssp, ssp, aa.x); ADD2(ssp, ssp, aa.y);
        }
        float a0 = hadd2(acc0), a1 = hadd2(acc1), a2 = hadd2(acc2), a3 = hadd2(acc3);
        float ss = hadd2(ssp);

        // reduce-scatter butterfly: octet o (= l>>3) ends holding full acc_o
        float p0 = (l & 16) ? a2 : a0;
        float q0 = (l & 16) ? a0 : a2;
        float p1 = (l & 16) ? a3 : a1;
        float q1 = (l & 16) ? a1 : a3;
        p0 += __shfl_xor_sync(~0u, q0, 16);
        p1 += __shfl_xor_sync(~0u, q1, 16);
        float pp = (l & 8) ? p1 : p0;
        float qq = (l & 8) ? p0 : p1;
        pp += __shfl_xor_sync(~0u, qq, 8);
        pp += __shfl_xor_sync(~0u, pp, 4);
        pp += __shfl_xor_sync(~0u, pp, 2);
        pp += __shfl_xor_sync(~0u, pp, 1);
        // regather: every lane builds (a0,a1,a2,a3) from octet representatives
        const int lb = l & 7;
        const float v0 = __shfl_sync(~0u, pp, lb);
        const float v1 = __shfl_sync(~0u, pp, 8 + lb);
        const float v2 = __shfl_sync(~0u, pp, 16 + lb);
        const float v3 = __shfl_sync(~0u, pp, 24 + lb);
        // full butterfly for ss (S_{t-1}; every lane needs it)
        #pragma unroll
        for (int o = 16; o; o >>= 1) ss += __shfl_xor_sync(~0u, ss, o);
        const float invS = __fdividef(1.f, ss);

        // push this warp's 4 scaled columns to all 8 CTAs (lane r -> peer r)
        if (l < 8) {
            float4 v;
            v.x = v0 * invS * e4.x;
            v.y = v1 * invS * e4.y;
            v.z = v2 * invS * e4.z;
            v.w = v3 * invS * e4.w;
            const unsigned daddr = rbuf + (unsigned)((sc * NS + colbase) * 4);
            st_async_v4(daddr, v, sc ? rmb1 : rmb0);
        }
        if (rank == 0 && tid == 0) L += __logf(ss);
        e4 = e4n;
        if (t >= 2) { if (sp) ph1 ^= 1; else ph0 ^= 1; }
    }

    // --- final S_{T-1} term: v_127 lives in slot 1 / mbar 1 (phase parity 1) ---
    if (w == 0) MBAR_WAIT_CLUSTER(mb1, ph1);
    __syncthreads();
    {
        const float* cur = buf[1];
        unsigned long long ssp = 0;
        #pragma unroll
        for (int k = 0; k < 4; k++) {
            ulonglong2 aa = *(const ulonglong2*)&cur[4 * l + 128 * k];
            ADD2(ssp, ssp, aa.x); ADD2(ssp, ssp, aa.y);
        }
        float ss = hadd2(ssp);
        #pragma unroll
        for (int o = 16; o; o >>= 1) ss += __shfl_xor_sync(~0u, ss, o);
        if (rank == 0 && tid == 0) {
            L += __logf(ss);
            g_L[g] = L;
        }
    }
    // align exits: no CTA leaves while a peer could still target its smem
    asm volatile("barrier.cluster.arrive.aligned;" ::: "memory");
    asm volatile("barrier.cluster.wait.aligned;"   ::: "memory");
}

// ===================== K5: loss = -mean_b L[b] ===================================
__global__ void k_final(float* __restrict__ out) {
    if (threadIdx.x == 0) {
        float s = 0.f;
        #pragma unroll
        for (int i = 0; i < NB; i++) s += g_L[i];
        out[0] = -s / (float)NB;
    }
}

// ===================== launch ====================================================
extern "C" void kernel_launch(void* const* d_in, const int* in_sizes, int n_in,
                              void* d_out, int out_size) {
    const float* em = nullptr;
    const float* tm = nullptr;
    const float* p  = nullptr;
    const int* ids  = nullptr;
    for (int i = 0; i < n_in; i++) {
        if (in_sizes[i] == NB * NT)      ids = (const int*)d_in[i];
        else if (in_sizes[i] == NS * NV) em  = (const float*)d_in[i];
        else if (in_sizes[i] == NS * NS) tm  = (const float*)d_in[i];
        else if (in_sizes[i] == NS)      p   = (const float*)d_in[i];
    }

    k_lse_em<<<NS, 256>>>(em);
    k_tm_pi<<<NS + 1, 128>>>(tm, p);
    k_gather<<<NB * NT, 128>>>(em, ids);

    {
        cudaLaunchConfig_t cfg = {};
        cfg.gridDim  = dim3(NB * 8, 1, 1);
        cfg.blockDim = dim3(512, 1, 1);
        cfg.dynamicSmemBytes = 0;
        cfg.stream = 0;
        cudaLaunchAttribute attrs[1];
        attrs[0].id = cudaLaunchAttributeClusterDimension;
        attrs[0].val.clusterDim.x = 8;
        attrs[0].val.clusterDim.y = 1;
        attrs[0].val.clusterDim.z = 1;
        cfg.attrs = attrs;
        cfg.numAttrs = 1;
        cudaLaunchKernelEx(&cfg, k_forward);
    }

    k_final<<<1, 32>>>((float*)d_out);
}